// round 2
// baseline (speedup 1.0000x reference)
#include <cuda_runtime.h>
#include <math.h>

#define BATCH 4
#define RAYS  4096
#define NCH   32
#define HRES  256
#define SC    48      // coarse samples
#define NI    48      // importance samples
#define NALL  96
#define HID   64

// Transposed planes: (B,3,H,W,C) so channels are contiguous (coalesced taps).
__device__ float g_planesT[(size_t)BATCH * 3 * HRES * HRES * NCH];

__device__ __forceinline__ float softplusf(float x) {
    return x > 20.0f ? x : log1pf(expf(x));
}
__device__ __forceinline__ float sigmoidf(float x) {
    return 1.0f / (1.0f + expf(-x));
}

// ---------------------------------------------------------------------------
// Transpose (B,3,C,H,W) -> (B,3,H,W,C)
// ---------------------------------------------------------------------------
__global__ void transpose_planes_kernel(const float* __restrict__ planes) {
    __shared__ float tile[32][33];
    const int bp  = blockIdx.y;              // 0..11
    const int hw0 = blockIdx.x * 32;         // spatial offset
    const float* src = planes + (size_t)bp * NCH * HRES * HRES;
    #pragma unroll
    for (int c = threadIdx.y; c < 32; c += 8)
        tile[c][threadIdx.x] = src[(size_t)c * (HRES * HRES) + hw0 + threadIdx.x];
    __syncthreads();
    float* dst = g_planesT + (size_t)bp * HRES * HRES * NCH;
    #pragma unroll
    for (int r = threadIdx.y; r < 32; r += 8)
        dst[(size_t)(hw0 + r) * NCH + threadIdx.x] = tile[threadIdx.x][r];
}

// ---------------------------------------------------------------------------
// Mega-kernel: one block (128 threads) per ray.
// ---------------------------------------------------------------------------
__global__ __launch_bounds__(128) void render_kernel(
    const float* __restrict__ ro, const float* __restrict__ rd,
    const float* __restrict__ zbg,
    const float* __restrict__ w1, const float* __restrict__ b1,
    const float* __restrict__ w2, const float* __restrict__ b2,
    const float* __restrict__ bw1, const float* __restrict__ bb1,
    const float* __restrict__ bw2, const float* __restrict__ bb2,
    float* __restrict__ out)
{
    const int tid  = threadIdx.x;
    const int warp = tid >> 5;
    const int lane = tid & 31;
    const int ray  = blockIdx.x;
    const int b    = ray / RAYS;

    __shared__ float sw1[NCH * HID];       // (32,64)
    __shared__ float sw2[HID * 33];        // (64,33)
    __shared__ float sb1[HID];
    __shared__ float sb2[33];
    __shared__ float rgb_s[NALL * NCH];    // raw rgb per sample
    __shared__ float sig_s[NALL];          // raw sigma per sample
    __shared__ float zfine[NI];
    __shared__ float wc[SC - 1];           // coarse march weights
    __shared__ float cdf[46];
    __shared__ float zmid[47];
    __shared__ float dall[NALL];
    __shared__ unsigned char perm[NALL];
    __shared__ float wall[NALL - 1];
    __shared__ float bgc[NCH];
    __shared__ float bgh[64];
    __shared__ float sfeat[4][NCH];
    __shared__ float shid[4][HID];
    __shared__ float s_o[3], s_d[3];
    __shared__ float s_T, s_wt, s_dacc;

    // --- load decode weights + ray data into smem ---
    for (int i = tid; i < NCH * HID; i += 128) sw1[i] = w1[i];
    for (int i = tid; i < HID * 33; i += 128)  sw2[i] = w2[i];
    if (tid < HID) sb1[tid] = b1[tid];
    if (tid < 33)  sb2[tid] = b2[tid];
    if (tid < 3) { s_o[tid] = ro[ray * 3 + tid]; s_d[tid] = rd[ray * 3 + tid]; }
    __syncthreads();

    const float STEP = (3.3f - 2.25f) / 47.0f;
    auto zc = [&](int i) -> float { return 2.25f + ((float)i + 0.5f) * STEP; };

    // --- background MLP (67 -> 64 -> 32), per ray ---
    if (tid < 64) {
        float acc = bb1[tid];
        acc = fmaf(s_d[0], bw1[tid],        acc);
        acc = fmaf(s_d[1], bw1[64 + tid],   acc);
        acc = fmaf(s_d[2], bw1[128 + tid],  acc);
        const float* zb = zbg + b * 64;
        #pragma unroll 8
        for (int i = 0; i < 64; i++)
            acc = fmaf(zb[i], bw1[(3 + i) * 64 + tid], acc);
        bgh[tid] = softplusf(acc);
    }
    __syncthreads();
    if (tid < 32) {
        float acc = bb2[tid];
        #pragma unroll 8
        for (int h = 0; h < 64; h++)
            acc = fmaf(bgh[h], bw2[h * 32 + tid], acc);
        bgc[tid] = sigmoidf(acc);
    }

    const float ox = s_o[0], oy = s_o[1], oz = s_o[2];
    const float dx = s_d[0], dy = s_d[1], dz = s_d[2];

    // --- sample planes + decode MLP for one depth t; warp-cooperative ---
    auto sample_decode = [&](int jsm, float t) {
        const float px = fmaf(t, dx, ox);
        const float py = fmaf(t, dy, oy);
        const float pz = fmaf(t, dz, oz);
        const float cx = 2.0f * px, cy = 2.0f * py, cz = 2.0f * pz;

        float feat = 0.0f;
        #pragma unroll
        for (int p = 0; p < 3; p++) {
            // plane0:(cx,cy) plane1:(cx,cz) plane2:(cz,cx)
            const float gx = (p == 2) ? cz : cx;
            const float gy = (p == 0) ? cy : ((p == 1) ? cz : cx);
            const float x = fmaf(gx + 1.0f, 128.0f, -0.5f);
            const float y = fmaf(gy + 1.0f, 128.0f, -0.5f);
            const float x0f = floorf(x), y0f = floorf(y);
            const float wx = x - x0f, wy = y - y0f;
            const int x0 = (int)x0f, y0 = (int)y0f;
            const float* base = g_planesT + (size_t)(b * 3 + p) * (HRES * HRES * NCH);
            auto tap = [&](int xi, int yi, float w) -> float {
                const bool v = ((unsigned)xi < 256u) && ((unsigned)yi < 256u);
                const int xcl = min(max(xi, 0), 255);
                const int ycl = min(max(yi, 0), 255);
                const float val = base[(((ycl << 8) + xcl) << 5) + lane];
                return v ? val * w : 0.0f;
            };
            feat += tap(x0,     y0,     (1.0f - wx) * (1.0f - wy));
            feat += tap(x0 + 1, y0,     wx * (1.0f - wy));
            feat += tap(x0,     y0 + 1, (1.0f - wx) * wy);
            feat += tap(x0 + 1, y0 + 1, wx * wy);
        }
        feat *= (1.0f / 3.0f);
        sfeat[warp][lane] = feat;
        __syncwarp();

        // hidden layer: lane computes units lane and lane+32
        float a0 = sb1[lane], a1 = sb1[lane + 32];
        #pragma unroll
        for (int c = 0; c < 32; c++) {
            const float f = sfeat[warp][c];
            a0 = fmaf(f, sw1[c * 64 + lane],      a0);
            a1 = fmaf(f, sw1[c * 64 + lane + 32], a1);
        }
        shid[warp][lane]      = softplusf(a0);
        shid[warp][lane + 32] = softplusf(a1);
        __syncwarp();

        // output layer: lane computes rgb channel `lane`; sigma warp-reduced
        float ar = sb2[1 + lane];
        #pragma unroll
        for (int h = 0; h < 64; h++)
            ar = fmaf(shid[warp][h], sw2[h * 33 + 1 + lane], ar);
        float as = fmaf(shid[warp][lane], sw2[lane * 33],
                        shid[warp][lane + 32] * sw2[(lane + 32) * 33]);
        #pragma unroll
        for (int off = 16; off; off >>= 1)
            as += __shfl_xor_sync(0xffffffffu, as, off);

        rgb_s[jsm * 32 + lane] = sigmoidf(ar) * 1.002f - 0.001f;
        if (lane == 0) sig_s[jsm] = as + sb2[0];
        __syncwarp();
    };

    // --- Phase A: coarse samples ---
    for (int j = warp; j < SC; j += 4) sample_decode(j, zc(j));
    __syncthreads();

    if (tid < 47) zmid[tid] = 0.5f * (zc(tid) + zc(tid + 1));

    // --- Phase B/C: coarse march + smoothed pdf/cdf (serial, thread 0) ---
    if (tid == 0) {
        float T = 1.0f;
        for (int i = 0; i < 47; i++) {
            const float dens  = softplusf(0.5f * (sig_s[i] + sig_s[i + 1]) - 1.0f);
            const float alpha = 1.0f - expf(-dens * STEP);
            wc[i] = alpha * T;
            T *= (1.0f - alpha + 1e-10f);
        }
        // smoothing: w'=maxpool(w+0.01), w''=0.5*(w'+w')+0.01; pdf over w''[1..45]
        float s = 0.0f;
        for (int k = 0; k < 45; k++) {
            const float a  = fmaxf(wc[k],     wc[k + 1]) + 0.01f;
            const float bb = fmaxf(wc[k + 1], wc[k + 2]) + 0.01f;
            const float v  = 0.5f * (a + bb) + 0.01f + 1e-5f;
            wall[k] = v;  // scratch
            s += v;
        }
        const float inv = 1.0f / s;
        cdf[0] = 0.0f;
        float acc = 0.0f;
        for (int k = 0; k < 45; k++) { acc += wall[k] * inv; cdf[k + 1] = acc; }
    }
    __syncthreads();

    // --- inverse-CDF sampling of 48 fine depths (sorted by construction) ---
    if (tid < NI) {
        const float u = ((float)tid + 0.5f) * (1.0f / 48.0f);
        int idx = 0;
        while (idx < 46 && cdf[idx] <= u) idx++;   // searchsorted right
        int below = idx - 1; if (below < 0) below = 0; if (below > 45) below = 45;
        int above = idx;     if (above > 45) above = 45;
        const float cb = cdf[below], ca = cdf[above];
        float den = ca - cb; if (den < 1e-5f) den = 1.0f;
        const float bbv = zmid[below], bav = zmid[above];
        zfine[tid] = fmaf((u - cb) / den, bav - bbv, bbv);
    }
    __syncthreads();

    // --- Phase D: fine samples ---
    for (int j = warp; j < NI; j += 4) sample_decode(SC + j, zfine[j]);
    __syncthreads();

    // --- Phase E: merge (both lists sorted; stable, coarse first on ties) ---
    if (tid == 0) {
        int i = 0, jf = 0;
        for (int k = 0; k < NALL; k++) {
            const float zcv = (i  < SC) ? zc(i)      : 3.4e38f;
            const float zfv = (jf < NI) ? zfine[jf]  : 3.4e38f;
            if (zcv <= zfv) { dall[k] = zcv; perm[k] = (unsigned char)i;        i++;  }
            else            { dall[k] = zfv; perm[k] = (unsigned char)(SC + jf); jf++; }
        }
        // final ray march (scalar part)
        float T = 1.0f, wt = 0.0f, dacc = 0.0f;
        for (int k = 0; k < NALL - 1; k++) {
            const float delta = dall[k + 1] - dall[k];
            const float dens  = softplusf(0.5f * (sig_s[perm[k]] + sig_s[perm[k + 1]]) - 1.0f);
            const float alpha = 1.0f - expf(-dens * delta);
            const float w = alpha * T;
            wall[k] = w;
            wt += w;
            dacc = fmaf(w, 0.5f * (dall[k] + dall[k + 1]), dacc);
            T *= (1.0f - alpha + 1e-10f);
        }
        s_T = T; s_wt = wt; s_dacc = dacc;
    }
    __syncthreads();

    // --- outputs ---
    float* out_rgb   = out;
    float* out_depth = out + (size_t)BATCH * RAYS * 32;
    float* out_wsum  = out + (size_t)BATCH * RAYS * 33;

    if (tid < 32) {
        float acc = 0.0f;
        for (int k = 0; k < NALL - 1; k++) {
            const int p0 = perm[k], p1 = perm[k + 1];
            acc = fmaf(wall[k], 0.5f * (rgb_s[p0 * 32 + tid] + rgb_s[p1 * 32 + tid]), acc);
        }
        acc = fmaf(s_T, bgc[tid], acc);
        out_rgb[(size_t)ray * 32 + tid] = acc * 2.0f - 1.0f;
    } else if (tid == 32) {
        float dv = s_dacc / s_wt;
        if (dv != dv) dv = INFINITY;              // nan -> inf
        const float ZMIN = 2.25f + 0.5f  * STEP;  // global depths.min()
        const float ZMAX = 2.25f + 47.5f * STEP;  // global depths.max()
        dv = fminf(fmaxf(dv, ZMIN), ZMAX);
        out_depth[ray] = dv;
        out_wsum[ray]  = s_wt;
    }
}

// ---------------------------------------------------------------------------
extern "C" void kernel_launch(void* const* d_in, const int* in_sizes, int n_in,
                              void* d_out, int out_size) {
    const float* planes = (const float*)d_in[0];
    const float* ro     = (const float*)d_in[1];
    const float* rd     = (const float*)d_in[2];
    const float* zbg    = (const float*)d_in[3];
    const float* w1     = (const float*)d_in[4];
    const float* b1     = (const float*)d_in[5];
    const float* w2     = (const float*)d_in[6];
    const float* b2     = (const float*)d_in[7];
    const float* bw1    = (const float*)d_in[8];
    const float* bb1    = (const float*)d_in[9];
    const float* bw2    = (const float*)d_in[10];
    const float* bb2    = (const float*)d_in[11];
    float* out = (float*)d_out;

    dim3 tgrid(HRES * HRES / 32, BATCH * 3);
    transpose_planes_kernel<<<tgrid, dim3(32, 8)>>>(planes);
    render_kernel<<<BATCH * RAYS, 128>>>(ro, rd, zbg, w1, b1, w2, b2,
                                         bw1, bb1, bw2, bb2, out);
}

// round 3
// speedup vs baseline: 1.2662x; 1.2662x over previous
#include <cuda_runtime.h>
#include <math.h>

#define BATCH 4
#define RAYS  4096
#define NCH   32
#define HRES  256
#define SC    48      // coarse samples
#define NI    48      // importance samples
#define NALL  96
#define HID   64

// Transposed planes: (B,3,H,W,C) so channels are contiguous (coalesced taps).
__device__ float g_planesT[(size_t)BATCH * 3 * HRES * HRES * NCH];

__device__ __forceinline__ float softplusf_fast(float x) {
    // log1p(exp(x)) = max(x,0) + log(1 + exp(-|x|))
    return fmaxf(x, 0.0f) + __logf(1.0f + __expf(-fabsf(x)));
}
__device__ __forceinline__ float sigmoidf_fast(float x) {
    return 1.0f / (1.0f + __expf(-x));
}
__device__ __forceinline__ float2 ffma2(float2 a, float2 b, float2 c) {
    unsigned long long ra = *reinterpret_cast<unsigned long long*>(&a);
    unsigned long long rb = *reinterpret_cast<unsigned long long*>(&b);
    unsigned long long rc = *reinterpret_cast<unsigned long long*>(&c);
    unsigned long long rd;
    asm("fma.rn.f32x2 %0, %1, %2, %3;" : "=l"(rd) : "l"(ra), "l"(rb), "l"(rc));
    return *reinterpret_cast<float2*>(&rd);
}

// ---------------------------------------------------------------------------
// Transpose (B,3,C,H,W) -> (B,3,H,W,C)
// ---------------------------------------------------------------------------
__global__ void transpose_planes_kernel(const float* __restrict__ planes) {
    __shared__ float tile[32][33];
    const int bp  = blockIdx.y;              // 0..11
    const int hw0 = blockIdx.x * 32;         // spatial offset
    const float* src = planes + (size_t)bp * NCH * HRES * HRES;
    #pragma unroll
    for (int c = threadIdx.y; c < 32; c += 8)
        tile[c][threadIdx.x] = src[(size_t)c * (HRES * HRES) + hw0 + threadIdx.x];
    __syncthreads();
    float* dst = g_planesT + (size_t)bp * HRES * HRES * NCH;
    #pragma unroll
    for (int r = threadIdx.y; r < 32; r += 8)
        dst[(size_t)(hw0 + r) * NCH + threadIdx.x] = tile[threadIdx.x][r];
}

// ---------------------------------------------------------------------------
// Mega-kernel: one block (128 threads) per ray.
// ---------------------------------------------------------------------------
__global__ __launch_bounds__(128) void render_kernel(
    const float* __restrict__ ro, const float* __restrict__ rd,
    const float* __restrict__ zbg,
    const float* __restrict__ w1, const float* __restrict__ b1,
    const float* __restrict__ w2, const float* __restrict__ b2,
    const float* __restrict__ bw1, const float* __restrict__ bb1,
    const float* __restrict__ bw2, const float* __restrict__ bb2,
    float* __restrict__ out)
{
    const int tid  = threadIdx.x;
    const int warp = tid >> 5;
    const int lane = tid & 31;
    const int ray  = blockIdx.x;
    const int b    = ray / RAYS;

    __shared__ float2 sw1p[32 * 32];     // (c,lane) -> (w1[c][lane], w1[c][lane+32])
    __shared__ float2 sw2p[32 * 32];     // (k,lane) -> (w2[2k][1+lane], w2[2k+1][1+lane])
    __shared__ float2 sw2s[32];          // lane -> (w2[lane][0], w2[lane+32][0])
    __shared__ float2 sb1p[32];          // (b1[lane], b1[lane+32])
    __shared__ float  sb2r[32];          // b2[1+lane]
    __shared__ float  rgb_s[NALL * NCH]; // raw rgb per sample
    __shared__ float  sig_s[NALL];       // raw sigma per sample
    __shared__ float  zfine[NI];
    __shared__ float  wc[SC - 1];        // coarse march weights
    __shared__ float  cdf[46];
    __shared__ float  zmid[47];
    __shared__ float  dall[NALL];
    __shared__ unsigned char perm[NALL];
    __shared__ float  wall[NALL - 1];
    __shared__ float  alpha_s[NALL - 1]; // parallel-computed alphas (reused)
    __shared__ float  bgc[NCH];
    __shared__ float  bgh[64];
    __shared__ float  shid[4][HID];      // hidden activations, per warp
    __shared__ float  s_o[3], s_d[3];
    __shared__ float  s_b2sig;
    __shared__ float  s_T, s_wt, s_dacc;

    // --- load + pack decode weights into smem ---
    for (int i = tid; i < 32 * 32; i += 128) {
        const int c = i >> 5, l = i & 31;
        sw1p[i] = make_float2(w1[c * 64 + l], w1[c * 64 + 32 + l]);
        sw2p[i] = make_float2(w2[(2 * c) * 33 + 1 + l], w2[(2 * c + 1) * 33 + 1 + l]);
    }
    if (tid < 32) {
        sw2s[tid] = make_float2(w2[tid * 33], w2[(tid + 32) * 33]);
        sb1p[tid] = make_float2(b1[tid], b1[tid + 32]);
        sb2r[tid] = b2[1 + tid];
    }
    if (tid == 0) s_b2sig = b2[0];
    if (tid < 3) { s_o[tid] = ro[ray * 3 + tid]; s_d[tid] = rd[ray * 3 + tid]; }
    __syncthreads();

    const float STEP = (3.3f - 2.25f) / 47.0f;
    auto zc = [&](int i) -> float { return 2.25f + ((float)i + 0.5f) * STEP; };

    // --- background MLP (67 -> 64 -> 32), per ray ---
    if (tid < 64) {
        float acc = bb1[tid];
        acc = fmaf(s_d[0], bw1[tid],        acc);
        acc = fmaf(s_d[1], bw1[64 + tid],   acc);
        acc = fmaf(s_d[2], bw1[128 + tid],  acc);
        const float* zb = zbg + b * 64;
        #pragma unroll 8
        for (int i = 0; i < 64; i++)
            acc = fmaf(zb[i], bw1[(3 + i) * 64 + tid], acc);
        bgh[tid] = softplusf_fast(acc);
    }
    __syncthreads();
    if (tid < 32) {
        float acc = bb2[tid];
        #pragma unroll 8
        for (int h = 0; h < 64; h++)
            acc = fmaf(bgh[h], bw2[h * 32 + tid], acc);
        bgc[tid] = sigmoidf_fast(acc);
    }

    const float ox = s_o[0], oy = s_o[1], oz = s_o[2];
    const float dx = s_d[0], dy = s_d[1], dz = s_d[2];

    // --- sample planes + decode MLP for one depth t; warp-cooperative ---
    auto sample_decode = [&](int jsm, float t) {
        const float px = fmaf(t, dx, ox);
        const float py = fmaf(t, dy, oy);
        const float pz = fmaf(t, dz, oz);
        const float cx = 2.0f * px, cy = 2.0f * py, cz = 2.0f * pz;

        float feat = 0.0f;
        #pragma unroll
        for (int p = 0; p < 3; p++) {
            // plane0:(cx,cy) plane1:(cx,cz) plane2:(cz,cx)
            const float gx = (p == 2) ? cz : cx;
            const float gy = (p == 0) ? cy : ((p == 1) ? cz : cx);
            const float x = fmaf(gx + 1.0f, 128.0f, -0.5f);
            const float y = fmaf(gy + 1.0f, 128.0f, -0.5f);
            const float x0f = floorf(x), y0f = floorf(y);
            const float wx = x - x0f, wy = y - y0f;
            const int x0 = (int)x0f, y0 = (int)y0f;
            const float* base = g_planesT + (size_t)(b * 3 + p) * (HRES * HRES * NCH);
            auto tap = [&](int xi, int yi, float w) -> float {
                const bool v = ((unsigned)xi < 256u) && ((unsigned)yi < 256u);
                const int xcl = min(max(xi, 0), 255);
                const int ycl = min(max(yi, 0), 255);
                const float val = __ldg(base + ((((ycl << 8) + xcl) << 5) + lane));
                return v ? val * w : 0.0f;
            };
            feat += tap(x0,     y0,     (1.0f - wx) * (1.0f - wy));
            feat += tap(x0 + 1, y0,     wx * (1.0f - wy));
            feat += tap(x0,     y0 + 1, (1.0f - wx) * wy);
            feat += tap(x0 + 1, y0 + 1, wx * wy);
        }
        feat *= (1.0f / 3.0f);

        // hidden layer: lane computes units (lane, lane+32) as packed f32x2
        float2 acc = sb1p[lane];
        #pragma unroll
        for (int c = 0; c < 32; c++) {
            const float f = __shfl_sync(0xffffffffu, feat, c);
            acc = ffma2(make_float2(f, f), sw1p[c * 32 + lane], acc);
        }
        const float h0 = softplusf_fast(acc.x);
        const float h1 = softplusf_fast(acc.y);
        shid[warp][lane]      = h0;
        shid[warp][lane + 32] = h1;
        __syncwarp();

        // output layer (rgb): packed over h-pairs
        const float2* shid2 = reinterpret_cast<const float2*>(shid[warp]);
        float2 acc2 = make_float2(0.0f, 0.0f);
        #pragma unroll
        for (int k = 0; k < 32; k++)
            acc2 = ffma2(shid2[k], sw2p[k * 32 + lane], acc2);
        const float ar = acc2.x + acc2.y + sb2r[lane];

        // sigma: warp-reduced
        const float2 sv = sw2s[lane];
        float as = fmaf(h0, sv.x, h1 * sv.y);
        #pragma unroll
        for (int off = 16; off; off >>= 1)
            as += __shfl_xor_sync(0xffffffffu, as, off);

        rgb_s[jsm * 32 + lane] = sigmoidf_fast(ar) * 1.002f - 0.001f;
        if (lane == 0) sig_s[jsm] = as + s_b2sig;
        __syncwarp();
    };

    // --- Phase A: coarse samples ---
    for (int j = warp; j < SC; j += 4) sample_decode(j, zc(j));
    __syncthreads();

    if (tid < 47) {
        zmid[tid] = 0.5f * (zc(tid) + zc(tid + 1));
        // parallel coarse-march alphas
        const float dens = softplusf_fast(0.5f * (sig_s[tid] + sig_s[tid + 1]) - 1.0f);
        alpha_s[tid] = 1.0f - __expf(-dens * STEP);
    }
    __syncthreads();

    // --- Phase B/C: coarse cumprod + smoothed pdf/cdf (cheap serial) ---
    if (tid == 0) {
        float T = 1.0f;
        #pragma unroll 4
        for (int i = 0; i < 47; i++) {
            const float a = alpha_s[i];
            wc[i] = a * T;
            T *= (1.0f - a + 1e-10f);
        }
        // smoothing: maxpool + blur + normalize -> cdf
        float s = 0.0f;
        #pragma unroll 4
        for (int k = 0; k < 45; k++) {
            const float a  = fmaxf(wc[k],     wc[k + 1]) + 0.01f;
            const float bb = fmaxf(wc[k + 1], wc[k + 2]) + 0.01f;
            const float v  = 0.5f * (a + bb) + 0.01f + 1e-5f;
            wall[k] = v;  // scratch
            s += v;
        }
        const float inv = 1.0f / s;
        cdf[0] = 0.0f;
        float acc = 0.0f;
        #pragma unroll 4
        for (int k = 0; k < 45; k++) { acc += wall[k] * inv; cdf[k + 1] = acc; }
    }
    __syncthreads();

    // --- inverse-CDF sampling of 48 fine depths (sorted by construction) ---
    if (tid < NI) {
        const float u = ((float)tid + 0.5f) * (1.0f / 48.0f);
        int idx = 0;
        while (idx < 46 && cdf[idx] <= u) idx++;   // searchsorted right
        int below = idx - 1; if (below < 0) below = 0; if (below > 45) below = 45;
        int above = idx;     if (above > 45) above = 45;
        const float cb = cdf[below], ca = cdf[above];
        float den = ca - cb; if (den < 1e-5f) den = 1.0f;
        const float bbv = zmid[below], bav = zmid[above];
        zfine[tid] = fmaf((u - cb) / den, bav - bbv, bbv);
    }
    __syncthreads();

    // --- Phase D: fine samples ---
    for (int j = warp; j < NI; j += 4) sample_decode(SC + j, zfine[j]);
    __syncthreads();

    // --- Phase E: parallel stable merge by rank-counting ---
    // coarse sample i goes to position i + #{fine < zc(i)}  (coarse first on ties)
    // fine   sample j goes to position j + #{coarse <= zfine[j]}
    if (tid < NALL) {
        if (tid < SC) {
            const float zv = zc(tid);
            int c = 0;
            #pragma unroll 8
            for (int k = 0; k < NI; k++) c += (zfine[k] < zv) ? 1 : 0;
            const int pos = tid + c;
            dall[pos] = zv; perm[pos] = (unsigned char)tid;
        } else {
            const int j = tid - SC;
            const float zv = zfine[j];
            int c = 0;
            #pragma unroll 8
            for (int k = 0; k < SC; k++) c += (zc(k) <= zv) ? 1 : 0;
            const int pos = j + c;
            dall[pos] = zv; perm[pos] = (unsigned char)(SC + j);
        }
    }
    __syncthreads();

    // parallel final-march alphas
    if (tid < NALL - 1) {
        const float delta = dall[tid + 1] - dall[tid];
        const float dens  = softplusf_fast(0.5f * (sig_s[perm[tid]] + sig_s[perm[tid + 1]]) - 1.0f);
        alpha_s[tid] = 1.0f - __expf(-dens * delta);
    }
    __syncthreads();

    // cheap serial cumprod + sums
    if (tid == 0) {
        float T = 1.0f, wt = 0.0f, dacc = 0.0f;
        #pragma unroll 4
        for (int k = 0; k < NALL - 1; k++) {
            const float a = alpha_s[k];
            const float w = a * T;
            wall[k] = w;
            wt += w;
            dacc = fmaf(w, 0.5f * (dall[k] + dall[k + 1]), dacc);
            T *= (1.0f - a + 1e-10f);
        }
        s_T = T; s_wt = wt; s_dacc = dacc;
    }
    __syncthreads();

    // --- outputs ---
    float* out_rgb   = out;
    float* out_depth = out + (size_t)BATCH * RAYS * 32;
    float* out_wsum  = out + (size_t)BATCH * RAYS * 33;

    if (tid < 32) {
        float acc = 0.0f;
        for (int k = 0; k < NALL - 1; k++) {
            const int p0 = perm[k], p1 = perm[k + 1];
            acc = fmaf(wall[k], 0.5f * (rgb_s[p0 * 32 + tid] + rgb_s[p1 * 32 + tid]), acc);
        }
        acc = fmaf(s_T, bgc[tid], acc);
        out_rgb[(size_t)ray * 32 + tid] = acc * 2.0f - 1.0f;
    } else if (tid == 32) {
        float dv = s_dacc / s_wt;
        if (dv != dv) dv = INFINITY;              // nan -> inf
        const float ZMIN = 2.25f + 0.5f  * STEP;  // global depths.min()
        const float ZMAX = 2.25f + 47.5f * STEP;  // global depths.max()
        dv = fminf(fmaxf(dv, ZMIN), ZMAX);
        out_depth[ray] = dv;
        out_wsum[ray]  = s_wt;
    }
}

// ---------------------------------------------------------------------------
extern "C" void kernel_launch(void* const* d_in, const int* in_sizes, int n_in,
                              void* d_out, int out_size) {
    const float* planes = (const float*)d_in[0];
    const float* ro     = (const float*)d_in[1];
    const float* rd     = (const float*)d_in[2];
    const float* zbg    = (const float*)d_in[3];
    const float* w1     = (const float*)d_in[4];
    const float* b1     = (const float*)d_in[5];
    const float* w2     = (const float*)d_in[6];
    const float* b2     = (const float*)d_in[7];
    const float* bw1    = (const float*)d_in[8];
    const float* bb1    = (const float*)d_in[9];
    const float* bw2    = (const float*)d_in[10];
    const float* bb2    = (const float*)d_in[11];
    float* out = (float*)d_out;

    dim3 tgrid(HRES * HRES / 32, BATCH * 3);
    transpose_planes_kernel<<<tgrid, dim3(32, 8)>>>(planes);
    render_kernel<<<BATCH * RAYS, 128>>>(ro, rd, zbg, w1, b1, w2, b2,
                                         bw1, bb1, bw2, bb2, out);
}